// round 13
// baseline (speedup 1.0000x reference)
#include <cuda_runtime.h>

// Problem dims (fixed by reference)
#define T0_R 8192
#define T0_C 4096
#define T1_R 4096
#define T1_C 2048
#define NG   1024
#define NMAP 512
#define CAP  128       // max rows/group; Binomial(8192,1/1024) max ~25, CAP=128 safe
#define ATILE 4        // column tiles per group in obsA (1024 cols each)

#define OBSA_BLKS (NG * ATILE)                 // 4096
#define P1_BLKS   T1_R                         // 4096
#define OBSB_BLKS NMAP                         // 512
#define LOSSC_BLKS 16
#define MEGA_BLKS (OBSA_BLKS + P1_BLKS + OBSB_BLKS + LOSSC_BLKS)   // 8720

// -------- device scratch (allocation-free, self-cleaning) --------
// Statically zero-init at load; invariant: every kernel_launch call both
// begins and ends with d_cnt/d_p2/d_loss/d_done_* zeroed.
//   d_cnt  : zeroed by mega epilogue (after all obsA tiles consumed it)
//   d_p2   : zeroed by lossC blocks (after consumption)
//   d_loss, d_done_* : zeroed by mega epilogue
//   d_p1, d_lst : fully overwritten each call
__device__ float  d_p2[T0_C];
__device__ float  d_p1[T1_R];
__device__ int    d_cnt[NG];
__device__ int    d_lst[NG * CAP];
__device__ double d_loss[3];     // [0]=sumsq loss_a, [1]=sumsq loss_b, [2]=sumsq loss_c
__device__ int    d_done_p1;
__device__ int    d_done_a;
__device__ int    d_done_all;

// -------- block reduction (sum), result valid on thread 0 --------
__device__ __forceinline__ float block_reduce_sum(float v) {
    __shared__ float s[32];
    int lane = threadIdx.x & 31;
    int wid  = threadIdx.x >> 5;
    #pragma unroll
    for (int o = 16; o > 0; o >>= 1) v += __shfl_down_sync(0xffffffffu, v, o);
    if (lane == 0) s[wid] = v;
    __syncthreads();
    int nw = blockDim.x >> 5;
    v = (threadIdx.x < nw) ? s[threadIdx.x] : 0.0f;
    if (wid == 0) {
        #pragma unroll
        for (int o = 16; o > 0; o >>= 1) v += __shfl_down_sync(0xffffffffu, v, o);
    }
    return v;
}

// spin until *ctr == target (t==0 polls with backoff, then block-wide fence)
__device__ __forceinline__ void wait_counter(volatile int* ctr, int target) {
    if (threadIdx.x == 0) {
        while (*ctr != target) __nanosleep(128);
    }
    __syncthreads();
    __threadfence();   // order subsequent reads after observed publication
}

// -------- 1) build per-group row lists (idx0 int32; d_cnt arrives zeroed) ----
__global__ void k_build(const int* __restrict__ idx0, int n_idx) {
    int i = blockIdx.x * blockDim.x + threadIdx.x;
    if (i < T0_R && i < n_idx) {
        int g = idx0[i];
        if (g < 0) g = 0;
        if (g >= NG) g = NG - 1;          // defensive clamp: no OOB ever
        int slot = atomicAdd(&d_cnt[g], 1);
        if (slot < CAP) d_lst[g * CAP + slot] = i;
    }
}

// -------- 2) mega: obsA | p1 | obsB(spin p1) | lossC(spin obsA) + epilogue ---
__global__ void __launch_bounds__(256) k_mega(const float* __restrict__ theta0,
                                              const float* __restrict__ obs0,
                                              const float* __restrict__ theta1,
                                              const float* __restrict__ mapping1,
                                              const float* __restrict__ obs1,
                                              const float* __restrict__ obs2,
                                              float* __restrict__ out) {
    int bid = blockIdx.x;
    int t = threadIdx.x;

    if (bid < OBSA_BLKS) {
        // ---- obsA: (group, col-tile); row list staged in SMEM (R12 body) ----
        __shared__ int s_rows[CAP];
        __shared__ int s_cnt;

        int g = bid & (NG - 1);
        int tile = bid >> 10;
        int c0 = tile * 1024;

        if (t == 0) {
            int c = d_cnt[g];
            s_cnt = (c > CAP) ? CAP : c;
        }
        if (t < CAP) s_rows[t] = d_lst[g * CAP + t];

        // prefetch obs0 segment while the row list lands
        const float* orow = obs0 + (size_t)g * T0_C + c0;
        float o[4];
        #pragma unroll
        for (int i = 0; i < 4; i++) o[i] = orow[t + i * 256];

        __syncthreads();
        int cnt = s_cnt;

        float acc[4];
        #pragma unroll
        for (int i = 0; i < 4; i++) acc[i] = 0.0f;

        int j = 0;
        for (; j + 4 <= cnt; j += 4) {
            const float* p0 = theta0 + (size_t)s_rows[j]     * T0_C + c0 + t;
            const float* p1 = theta0 + (size_t)s_rows[j + 1] * T0_C + c0 + t;
            const float* p2 = theta0 + (size_t)s_rows[j + 2] * T0_C + c0 + t;
            const float* p3 = theta0 + (size_t)s_rows[j + 3] * T0_C + c0 + t;
            float v[16];
            #pragma unroll
            for (int i = 0; i < 4; i++) v[i]      = __ldcs(p0 + i * 256);
            #pragma unroll
            for (int i = 0; i < 4; i++) v[4 + i]  = __ldcs(p1 + i * 256);
            #pragma unroll
            for (int i = 0; i < 4; i++) v[8 + i]  = __ldcs(p2 + i * 256);
            #pragma unroll
            for (int i = 0; i < 4; i++) v[12 + i] = __ldcs(p3 + i * 256);
            #pragma unroll
            for (int i = 0; i < 4; i++)
                acc[i] += __expf(v[i]) + __expf(v[4 + i]) + __expf(v[8 + i]) + __expf(v[12 + i]);
        }
        for (; j + 2 <= cnt; j += 2) {
            const float* p0 = theta0 + (size_t)s_rows[j]     * T0_C + c0 + t;
            const float* p1 = theta0 + (size_t)s_rows[j + 1] * T0_C + c0 + t;
            float v[8];
            #pragma unroll
            for (int i = 0; i < 4; i++) v[i]     = __ldcs(p0 + i * 256);
            #pragma unroll
            for (int i = 0; i < 4; i++) v[4 + i] = __ldcs(p1 + i * 256);
            #pragma unroll
            for (int i = 0; i < 4; i++) acc[i] += __expf(v[i]) + __expf(v[4 + i]);
        }
        if (j < cnt) {
            const float* p0 = theta0 + (size_t)s_rows[j] * T0_C + c0 + t;
            float v[4];
            #pragma unroll
            for (int i = 0; i < 4; i++) v[i] = __ldcs(p0 + i * 256);
            #pragma unroll
            for (int i = 0; i < 4; i++) acc[i] += __expf(v[i]);
        }

        float local = 0.0f;
        #pragma unroll
        for (int i = 0; i < 4; i++) {
            int c = t + i * 256;
            atomicAdd(&d_p2[c0 + c], acc[i]);
            float diff = o[i] - acc[i];
            local += diff * diff;
        }
        float tot = block_reduce_sum(local);
        if (t == 0) {
            atomicAdd(&d_loss[0], (double)tot);
            __threadfence();
            atomicAdd(&d_done_a, 1);      // publish this block's d_p2 contribution
        }
    } else if (bid < OBSA_BLKS + P1_BLKS) {
        // ---- p1: rowsum of exp(theta1), 8 batched scalar loads ----
        int r = bid - OBSA_BLKS;
        const float* tr = theta1 + (size_t)r * T1_C + t;
        float v[8];
        #pragma unroll
        for (int i = 0; i < 8; i++) v[i] = __ldcs(tr + i * 256);
        float local = 0.0f;
        #pragma unroll
        for (int i = 0; i < 8; i++) local += __expf(v[i]);
        float tot = block_reduce_sum(local);
        if (t == 0) {
            d_p1[r] = tot;
            __threadfence();
            atomicAdd(&d_done_p1, 1);     // publish d_p1[r]
        }
    } else if (bid < OBSA_BLKS + P1_BLKS + OBSB_BLKS) {
        // ---- obsB: mapping1 @ p1 + loss_b (waits for all p1 blocks) ----
        int b = bid - (OBSA_BLKS + P1_BLKS);
        wait_counter(&d_done_p1, P1_BLKS);
        const float* mrow = mapping1 + (size_t)b * T1_R + t;
        float m[16], p[16];
        #pragma unroll
        for (int i = 0; i < 16; i++) m[i] = __ldcs(mrow + i * 256);
        #pragma unroll
        for (int i = 0; i < 16; i++) p[i] = __ldcg(&d_p1[t + i * 256]);  // bypass L1: same launch
        float local = 0.0f;
        #pragma unroll
        for (int i = 0; i < 16; i++) local += m[i] * p[i];
        float tot = block_reduce_sum(local);
        if (t == 0) {
            float diff = obs1[b] - tot;
            atomicAdd(&d_loss[1], (double)(diff * diff));
        }
    } else {
        // ---- lossC: (obs2 - p2)^2 slices (waits for all obsA blocks) ----
        int c = (bid - (OBSA_BLKS + P1_BLKS + OBSB_BLKS)) * 256 + t;
        wait_counter(&d_done_a, OBSA_BLKS);
        float diff = obs2[c] - __ldcg(&d_p2[c]);   // bypass L1: same launch
        d_p2[c] = 0.0f;                   // self-clean for next call
        float tot = block_reduce_sum(diff * diff);
        if (t == 0) atomicAdd(&d_loss[2], (double)tot);
    }

    // ---- epilogue: last-ticket block combines + resets scratch ----
    __shared__ int is_last;
    if (t == 0) {
        __threadfence();
        int ticket = atomicAdd(&d_done_all, 1);
        is_last = (ticket == MEGA_BLKS - 1);
    }
    __syncthreads();
    if (is_last) {
        __threadfence();
        #pragma unroll
        for (int i = 0; i < NG / 256; i++) d_cnt[t + i * 256] = 0;  // self-clean
        if (t == 0) {
            double la = *((volatile double*)&d_loss[0]);
            double lb = *((volatile double*)&d_loss[1]);
            double lc = *((volatile double*)&d_loss[2]);
            double loss_a = la / ((double)NG * (double)T0_C);
            double loss_b = lb / (double)NMAP;
            double loss_c = 0.5 * (lc / (double)T0_C);
            out[0] = (float)((loss_a + loss_b + loss_c) / 3.0);
            d_loss[0] = 0.0;              // self-clean for next call
            d_loss[1] = 0.0;
            d_loss[2] = 0.0;
            d_done_p1 = 0;
            d_done_a  = 0;
            d_done_all = 0;
        }
    }
}

extern "C" void kernel_launch(void* const* d_in, const int* in_sizes, int n_in,
                              void* d_out, int out_size) {
    const float* theta0   = (const float*)d_in[0];
    const float* theta1   = (const float*)d_in[1];
    const float* obs0     = (const float*)d_in[2];
    const float* obs1     = (const float*)d_in[3];
    const float* obs2     = (const float*)d_in[4];
    const int*   idx0     = (const int*)d_in[5];   // int32: JAX x64 disabled
    const float* mapping1 = (const float*)d_in[6];
    float* out = (float*)d_out;

    k_build<<<(T0_R + 255) / 256, 256>>>(idx0, in_sizes[5]);
    k_mega<<<MEGA_BLKS, 256>>>(theta0, obs0, theta1, mapping1, obs1, obs2, out);
}

// round 14
// speedup vs baseline: 1.1149x; 1.1149x over previous
#include <cuda_runtime.h>

// Problem dims (fixed by reference)
#define T0_R 8192
#define T0_C 4096
#define T1_R 4096
#define T1_C 2048
#define NG   1024
#define NMAP 512
#define CAP  128       // max rows/group; Binomial(8192,1/1024) max ~25, CAP=128 safe
#define ATILE 4        // column tiles per group in obsA (1024 cols each)

#define BUILD_BLKS 32
#define A_BLKS (BUILD_BLKS + T1_R)             // launch A: build + p1
#define OBSA_BLKS (NG * ATILE)                 // 4096
#define LOSSC_BLKS 16
#define C_BLKS (NMAP + LOSSC_BLKS)             // launch C: obsB + lossC (+epilogue)

// -------- device scratch (allocation-free, self-cleaning) --------
// Statically zero-init at load; invariant: every kernel_launch call both
// begins and ends with d_cnt/d_p2/d_loss/d_done_all zeroed.
//   d_cnt  : zeroed by launch-C epilogue (obsA consumed it in launch B)
//   d_p2   : zeroed by lossC blocks (after consumption)
//   d_loss, d_done_all : zeroed by launch-C epilogue
//   d_p1, d_lst : fully overwritten each call
__device__ float  d_p2[T0_C];
__device__ float  d_p1[T1_R];
__device__ int    d_cnt[NG];
__device__ int    d_lst[NG * CAP];
__device__ double d_loss[3];     // [0]=sumsq loss_a, [1]=sumsq loss_b, [2]=sumsq loss_c
__device__ int    d_done_all;

// -------- block reduction (sum), result valid on thread 0 --------
__device__ __forceinline__ float block_reduce_sum(float v) {
    __shared__ float s[32];
    int lane = threadIdx.x & 31;
    int wid  = threadIdx.x >> 5;
    #pragma unroll
    for (int o = 16; o > 0; o >>= 1) v += __shfl_down_sync(0xffffffffu, v, o);
    if (lane == 0) s[wid] = v;
    __syncthreads();
    int nw = blockDim.x >> 5;
    v = (threadIdx.x < nw) ? s[threadIdx.x] : 0.0f;
    if (wid == 0) {
        #pragma unroll
        for (int o = 16; o > 0; o >>= 1) v += __shfl_down_sync(0xffffffffu, v, o);
    }
    return v;
}

// -------- Launch A: build (32 blks) + p1 (4096 blks) — independent ---------
__global__ void __launch_bounds__(256) k_buildp1(const int* __restrict__ idx0,
                                                 int n_idx,
                                                 const float* __restrict__ theta1) {
    int bid = blockIdx.x;
    int t = threadIdx.x;
    if (bid < BUILD_BLKS) {
        // ---- build per-group row lists (d_cnt arrives zeroed) ----
        int i = bid * 256 + t;
        if (i < T0_R && i < n_idx) {
            int g = idx0[i];
            if (g < 0) g = 0;
            if (g >= NG) g = NG - 1;      // defensive clamp: no OOB ever
            int slot = atomicAdd(&d_cnt[g], 1);
            if (slot < CAP) d_lst[g * CAP + slot] = i;
        }
    } else {
        // ---- p1: rowsum of exp(theta1), 8 batched scalar loads ----
        int r = bid - BUILD_BLKS;
        const float* tr = theta1 + (size_t)r * T1_C + t;
        float v[8];
        #pragma unroll
        for (int i = 0; i < 8; i++) v[i] = __ldcs(tr + i * 256);
        float local = 0.0f;
        #pragma unroll
        for (int i = 0; i < 8; i++) local += __expf(v[i]);
        float tot = block_reduce_sum(local);
        if (t == 0) d_p1[r] = tot;
    }
}

// -------- Launch B: obsA (R12 body verbatim) -------------------------------
// grid = NG*ATILE. unit u: g = u & 1023, tile = u >> 10. Row list staged in
// SMEM once so the streaming loop has no global gather gating addresses.
__global__ void __launch_bounds__(256) k_obsA(const float* __restrict__ theta0,
                                              const float* __restrict__ obs0) {
    __shared__ int s_rows[CAP];
    __shared__ int s_cnt;

    int u = blockIdx.x;
    int g = u & (NG - 1);
    int tile = u >> 10;
    int t = threadIdx.x;
    int c0 = tile * 1024;

    if (t == 0) {
        int c = d_cnt[g];
        s_cnt = (c > CAP) ? CAP : c;
    }
    if (t < CAP) s_rows[t] = d_lst[g * CAP + t];

    // prefetch obs0 segment while the row list lands
    const float* orow = obs0 + (size_t)g * T0_C + c0;
    float o[4];
    #pragma unroll
    for (int i = 0; i < 4; i++) o[i] = orow[t + i * 256];

    __syncthreads();
    int cnt = s_cnt;

    float acc[4];
    #pragma unroll
    for (int i = 0; i < 4; i++) acc[i] = 0.0f;

    int j = 0;
    for (; j + 4 <= cnt; j += 4) {
        const float* p0 = theta0 + (size_t)s_rows[j]     * T0_C + c0 + t;
        const float* p1 = theta0 + (size_t)s_rows[j + 1] * T0_C + c0 + t;
        const float* p2 = theta0 + (size_t)s_rows[j + 2] * T0_C + c0 + t;
        const float* p3 = theta0 + (size_t)s_rows[j + 3] * T0_C + c0 + t;
        float v[16];
        #pragma unroll
        for (int i = 0; i < 4; i++) v[i]      = __ldcs(p0 + i * 256);
        #pragma unroll
        for (int i = 0; i < 4; i++) v[4 + i]  = __ldcs(p1 + i * 256);
        #pragma unroll
        for (int i = 0; i < 4; i++) v[8 + i]  = __ldcs(p2 + i * 256);
        #pragma unroll
        for (int i = 0; i < 4; i++) v[12 + i] = __ldcs(p3 + i * 256);
        #pragma unroll
        for (int i = 0; i < 4; i++)
            acc[i] += __expf(v[i]) + __expf(v[4 + i]) + __expf(v[8 + i]) + __expf(v[12 + i]);
    }
    for (; j + 2 <= cnt; j += 2) {
        const float* p0 = theta0 + (size_t)s_rows[j]     * T0_C + c0 + t;
        const float* p1 = theta0 + (size_t)s_rows[j + 1] * T0_C + c0 + t;
        float v[8];
        #pragma unroll
        for (int i = 0; i < 4; i++) v[i]     = __ldcs(p0 + i * 256);
        #pragma unroll
        for (int i = 0; i < 4; i++) v[4 + i] = __ldcs(p1 + i * 256);
        #pragma unroll
        for (int i = 0; i < 4; i++) acc[i] += __expf(v[i]) + __expf(v[4 + i]);
    }
    if (j < cnt) {
        const float* p0 = theta0 + (size_t)s_rows[j] * T0_C + c0 + t;
        float v[4];
        #pragma unroll
        for (int i = 0; i < 4; i++) v[i] = __ldcs(p0 + i * 256);
        #pragma unroll
        for (int i = 0; i < 4; i++) acc[i] += __expf(v[i]);
    }

    float local = 0.0f;
    #pragma unroll
    for (int i = 0; i < 4; i++) {
        int c = t + i * 256;
        atomicAdd(&d_p2[c0 + c], acc[i]);
        float diff = o[i] - acc[i];
        local += diff * diff;
    }
    float tot = block_reduce_sum(local);
    if (t == 0) atomicAdd(&d_loss[0], (double)tot);
}

// -------- Launch C: obsB (512) + lossC (16) + last-ticket final ------------
__global__ void __launch_bounds__(256) k_tail(const float* __restrict__ mapping1,
                                              const float* __restrict__ obs1,
                                              const float* __restrict__ obs2,
                                              float* __restrict__ out) {
    int b = blockIdx.x;
    int t = threadIdx.x;
    if (b < NMAP) {
        // ---- obsB: mapping1 @ p1 + loss_b (p1 complete: prior launch) ----
        const float* mrow = mapping1 + (size_t)b * T1_R + t;
        float m[16], p[16];
        #pragma unroll
        for (int i = 0; i < 16; i++) m[i] = __ldcs(mrow + i * 256);
        #pragma unroll
        for (int i = 0; i < 16; i++) p[i] = d_p1[t + i * 256];
        float local = 0.0f;
        #pragma unroll
        for (int i = 0; i < 16; i++) local += m[i] * p[i];
        float tot = block_reduce_sum(local);
        if (t == 0) {
            float diff = obs1[b] - tot;
            atomicAdd(&d_loss[1], (double)(diff * diff));
        }
    } else {
        // ---- lossC: (obs2 - p2)^2 slice (p2 complete: prior launch) ----
        int c = (b - NMAP) * 256 + t;
        float diff = obs2[c] - d_p2[c];
        d_p2[c] = 0.0f;                   // self-clean for next call
        float tot = block_reduce_sum(diff * diff);
        if (t == 0) atomicAdd(&d_loss[2], (double)tot);
    }

    // ---- epilogue: last-ticket block combines + resets scratch ----
    __shared__ int is_last;
    if (t == 0) {
        __threadfence();
        int ticket = atomicAdd(&d_done_all, 1);
        is_last = (ticket == C_BLKS - 1);
    }
    __syncthreads();
    if (is_last) {
        __threadfence();
        #pragma unroll
        for (int i = 0; i < NG / 256; i++) d_cnt[t + i * 256] = 0;  // self-clean
        if (t == 0) {
            double la = *((volatile double*)&d_loss[0]);
            double lb = *((volatile double*)&d_loss[1]);
            double lc = *((volatile double*)&d_loss[2]);
            double loss_a = la / ((double)NG * (double)T0_C);
            double loss_b = lb / (double)NMAP;
            double loss_c = 0.5 * (lc / (double)T0_C);
            out[0] = (float)((loss_a + loss_b + loss_c) / 3.0);
            d_loss[0] = 0.0;              // self-clean for next call
            d_loss[1] = 0.0;
            d_loss[2] = 0.0;
            d_done_all = 0;
        }
    }
}

extern "C" void kernel_launch(void* const* d_in, const int* in_sizes, int n_in,
                              void* d_out, int out_size) {
    const float* theta0   = (const float*)d_in[0];
    const float* theta1   = (const float*)d_in[1];
    const float* obs0     = (const float*)d_in[2];
    const float* obs1     = (const float*)d_in[3];
    const float* obs2     = (const float*)d_in[4];
    const int*   idx0     = (const int*)d_in[5];   // int32: JAX x64 disabled
    const float* mapping1 = (const float*)d_in[6];
    float* out = (float*)d_out;

    k_buildp1<<<A_BLKS, 256>>>(idx0, in_sizes[5], theta1);
    k_obsA<<<OBSA_BLKS, 256>>>(theta0, obs0);
    k_tail<<<C_BLKS, 256>>>(mapping1, obs1, obs2, out);
}

// round 15
// speedup vs baseline: 1.1693x; 1.0487x over previous
#include <cuda_runtime.h>

// Problem dims (fixed by reference)
#define T0_R 8192
#define T0_C 4096
#define T1_R 4096
#define T1_C 2048
#define NG   1024
#define NMAP 512
#define CAP  128       // max rows/group; Binomial(8192,1/1024) max ~25, CAP=128 safe
#define ATILE 4        // column tiles per group in obsA (1024 cols each)

#define BUILD_BLKS 32
#define P1_BLKS (T1_R / 2)                     // 2048: two rows per block
#define A_BLKS (BUILD_BLKS + P1_BLKS)          // launch A
#define OBSA_BLKS (NG * ATILE)                 // 4096
#define B_BLKS (OBSA_BLKS + NMAP)              // launch B: obsA + obsB
#define LOSSC_BLKS 16
#define C_BLKS LOSSC_BLKS                      // launch C: lossC + epilogue

// -------- device scratch (allocation-free, self-cleaning) --------
// Statically zero-init at load; invariant: every kernel_launch call both
// begins and ends with d_cnt/d_p2/d_loss/d_done_all zeroed.
//   d_cnt  : zeroed by launch-C epilogue (obsA consumed it in launch B)
//   d_p2   : zeroed by lossC blocks (after consumption)
//   d_loss, d_done_all : zeroed by launch-C epilogue
//   d_p1, d_lst : fully overwritten each call
__device__ float  d_p2[T0_C];
__device__ float  d_p1[T1_R];
__device__ int    d_cnt[NG];
__device__ int    d_lst[NG * CAP];
__device__ double d_loss[3];     // [0]=sumsq loss_a, [1]=sumsq loss_b, [2]=sumsq loss_c
__device__ int    d_done_all;

// -------- block reduction (sum), result valid on thread 0 --------
__device__ __forceinline__ float block_reduce_sum(float v) {
    __shared__ float s[32];
    int lane = threadIdx.x & 31;
    int wid  = threadIdx.x >> 5;
    #pragma unroll
    for (int o = 16; o > 0; o >>= 1) v += __shfl_down_sync(0xffffffffu, v, o);
    if (lane == 0) s[wid] = v;
    __syncthreads();
    int nw = blockDim.x >> 5;
    v = (threadIdx.x < nw) ? s[threadIdx.x] : 0.0f;
    if (wid == 0) {
        #pragma unroll
        for (int o = 16; o > 0; o >>= 1) v += __shfl_down_sync(0xffffffffu, v, o);
    }
    return v;
}

// -------- Launch A: build (32 blks) + p1 (2048 blks, 2 rows each) ----------
__global__ void __launch_bounds__(256) k_buildp1(const int* __restrict__ idx0,
                                                 int n_idx,
                                                 const float* __restrict__ theta1) {
    int bid = blockIdx.x;
    int t = threadIdx.x;
    if (bid < BUILD_BLKS) {
        // ---- build per-group row lists (d_cnt arrives zeroed) ----
        int i = bid * 256 + t;
        if (i < T0_R && i < n_idx) {
            int g = idx0[i];
            if (g < 0) g = 0;
            if (g >= NG) g = NG - 1;      // defensive clamp: no OOB ever
            int slot = atomicAdd(&d_cnt[g], 1);
            if (slot < CAP) d_lst[g * CAP + slot] = i;
        }
    } else {
        // ---- p1: two rows per block; 128 threads/row x 16 loads (MLP=16) ----
        __shared__ float s[8];
        int b = bid - BUILD_BLKS;
        int half = t >> 7;                // 0 or 1
        int tt = t & 127;
        int r = 2 * b + half;
        const float* tr = theta1 + (size_t)r * T1_C + tt;
        float v[16];
        #pragma unroll
        for (int i = 0; i < 16; i++) v[i] = __ldcs(tr + i * 128);
        float local = 0.0f;
        #pragma unroll
        for (int i = 0; i < 16; i++) local += __expf(v[i]);
        // warp reduce, then 4-warp combine per half
        #pragma unroll
        for (int o = 16; o > 0; o >>= 1) local += __shfl_down_sync(0xffffffffu, local, o);
        int wid = t >> 5;
        if ((t & 31) == 0) s[wid] = local;
        __syncthreads();
        if (t == 0)   d_p1[2 * b]     = s[0] + s[1] + s[2] + s[3];
        if (t == 128) d_p1[2 * b + 1] = s[4] + s[5] + s[6] + s[7];
    }
}

// -------- Launch B: obsA (4096, R12 body) + obsB (512, needs only p1) ------
__global__ void __launch_bounds__(256) k_main(const float* __restrict__ theta0,
                                              const float* __restrict__ obs0,
                                              const float* __restrict__ mapping1,
                                              const float* __restrict__ obs1) {
    int bid = blockIdx.x;
    int t = threadIdx.x;

    if (bid < OBSA_BLKS) {
        // ---- obsA: (group, col-tile); row list staged in SMEM ----
        __shared__ int s_rows[CAP];
        __shared__ int s_cnt;

        int g = bid & (NG - 1);
        int tile = bid >> 10;
        int c0 = tile * 1024;

        if (t == 0) {
            int c = d_cnt[g];
            s_cnt = (c > CAP) ? CAP : c;
        }
        if (t < CAP) s_rows[t] = d_lst[g * CAP + t];

        // prefetch obs0 segment while the row list lands
        const float* orow = obs0 + (size_t)g * T0_C + c0;
        float o[4];
        #pragma unroll
        for (int i = 0; i < 4; i++) o[i] = orow[t + i * 256];

        __syncthreads();
        int cnt = s_cnt;

        float acc[4];
        #pragma unroll
        for (int i = 0; i < 4; i++) acc[i] = 0.0f;

        int j = 0;
        for (; j + 4 <= cnt; j += 4) {
            const float* p0 = theta0 + (size_t)s_rows[j]     * T0_C + c0 + t;
            const float* p1 = theta0 + (size_t)s_rows[j + 1] * T0_C + c0 + t;
            const float* p2 = theta0 + (size_t)s_rows[j + 2] * T0_C + c0 + t;
            const float* p3 = theta0 + (size_t)s_rows[j + 3] * T0_C + c0 + t;
            float v[16];
            #pragma unroll
            for (int i = 0; i < 4; i++) v[i]      = __ldcs(p0 + i * 256);
            #pragma unroll
            for (int i = 0; i < 4; i++) v[4 + i]  = __ldcs(p1 + i * 256);
            #pragma unroll
            for (int i = 0; i < 4; i++) v[8 + i]  = __ldcs(p2 + i * 256);
            #pragma unroll
            for (int i = 0; i < 4; i++) v[12 + i] = __ldcs(p3 + i * 256);
            #pragma unroll
            for (int i = 0; i < 4; i++)
                acc[i] += __expf(v[i]) + __expf(v[4 + i]) + __expf(v[8 + i]) + __expf(v[12 + i]);
        }
        for (; j + 2 <= cnt; j += 2) {
            const float* p0 = theta0 + (size_t)s_rows[j]     * T0_C + c0 + t;
            const float* p1 = theta0 + (size_t)s_rows[j + 1] * T0_C + c0 + t;
            float v[8];
            #pragma unroll
            for (int i = 0; i < 4; i++) v[i]     = __ldcs(p0 + i * 256);
            #pragma unroll
            for (int i = 0; i < 4; i++) v[4 + i] = __ldcs(p1 + i * 256);
            #pragma unroll
            for (int i = 0; i < 4; i++) acc[i] += __expf(v[i]) + __expf(v[4 + i]);
        }
        if (j < cnt) {
            const float* p0 = theta0 + (size_t)s_rows[j] * T0_C + c0 + t;
            float v[4];
            #pragma unroll
            for (int i = 0; i < 4; i++) v[i] = __ldcs(p0 + i * 256);
            #pragma unroll
            for (int i = 0; i < 4; i++) acc[i] += __expf(v[i]);
        }

        float local = 0.0f;
        #pragma unroll
        for (int i = 0; i < 4; i++) {
            int c = t + i * 256;
            atomicAdd(&d_p2[c0 + c], acc[i]);
            float diff = o[i] - acc[i];
            local += diff * diff;
        }
        float tot = block_reduce_sum(local);
        if (t == 0) atomicAdd(&d_loss[0], (double)tot);
    } else {
        // ---- obsB: mapping1 @ p1 + loss_b (p1 complete: prior launch) ----
        int b = bid - OBSA_BLKS;
        const float* mrow = mapping1 + (size_t)b * T1_R + t;
        float m[16], p[16];
        #pragma unroll
        for (int i = 0; i < 16; i++) m[i] = __ldcs(mrow + i * 256);
        #pragma unroll
        for (int i = 0; i < 16; i++) p[i] = d_p1[t + i * 256];
        float local = 0.0f;
        #pragma unroll
        for (int i = 0; i < 16; i++) local += m[i] * p[i];
        float tot = block_reduce_sum(local);
        if (t == 0) {
            float diff = obs1[b] - tot;
            atomicAdd(&d_loss[1], (double)(diff * diff));
        }
    }
}

// -------- Launch C: lossC (16 blks) + last-ticket final combine ------------
__global__ void __launch_bounds__(256) k_tail(const float* __restrict__ obs2,
                                              float* __restrict__ out) {
    int t = threadIdx.x;
    int c = blockIdx.x * 256 + t;
    float diff = obs2[c] - d_p2[c];
    d_p2[c] = 0.0f;                       // self-clean for next call
    float tot = block_reduce_sum(diff * diff);
    if (t == 0) atomicAdd(&d_loss[2], (double)tot);

    // ---- epilogue: last-ticket block combines + resets scratch ----
    __shared__ int is_last;
    if (t == 0) {
        __threadfence();
        int ticket = atomicAdd(&d_done_all, 1);
        is_last = (ticket == C_BLKS - 1);
    }
    __syncthreads();
    if (is_last) {
        __threadfence();
        #pragma unroll
        for (int i = 0; i < NG / 256; i++) d_cnt[t + i * 256] = 0;  // self-clean
        if (t == 0) {
            double la = *((volatile double*)&d_loss[0]);
            double lb = *((volatile double*)&d_loss[1]);
            double lc = *((volatile double*)&d_loss[2]);
            double loss_a = la / ((double)NG * (double)T0_C);
            double loss_b = lb / (double)NMAP;
            double loss_c = 0.5 * (lc / (double)T0_C);
            out[0] = (float)((loss_a + loss_b + loss_c) / 3.0);
            d_loss[0] = 0.0;              // self-clean for next call
            d_loss[1] = 0.0;
            d_loss[2] = 0.0;
            d_done_all = 0;
        }
    }
}

extern "C" void kernel_launch(void* const* d_in, const int* in_sizes, int n_in,
                              void* d_out, int out_size) {
    const float* theta0   = (const float*)d_in[0];
    const float* theta1   = (const float*)d_in[1];
    const float* obs0     = (const float*)d_in[2];
    const float* obs1     = (const float*)d_in[3];
    const float* obs2     = (const float*)d_in[4];
    const int*   idx0     = (const int*)d_in[5];   // int32: JAX x64 disabled
    const float* mapping1 = (const float*)d_in[6];
    float* out = (float*)d_out;

    k_buildp1<<<A_BLKS, 256>>>(idx0, in_sizes[5], theta1);
    k_main<<<B_BLKS, 256>>>(theta0, obs0, mapping1, obs1);
    k_tail<<<C_BLKS, 256>>>(obs2, out);
}

// round 16
// speedup vs baseline: 1.3155x; 1.1251x over previous
#include <cuda_runtime.h>

// Problem dims (fixed by reference)
#define T0_R 8192
#define T0_C 4096
#define T1_R 4096
#define T1_C 2048
#define NG   1024
#define NMAP 512
#define CAP  128       // max rows/group; Binomial(8192,1/1024) max ~25, CAP=128 safe
#define ATILE 4        // column tiles per group in obsA (1024 cols each)

#define BUILD_BLKS 32
#define P1_BLKS (T1_R / 2)                     // 2048: two rows per block
#define A_BLKS (BUILD_BLKS + P1_BLKS)          // launch A
#define OBSA_BLKS (NG * ATILE)                 // 4096
#define B_BLKS (OBSA_BLKS + NMAP)              // launch B: obsA + obsB
#define LOSSC_BLKS 16
#define C_BLKS LOSSC_BLKS                      // launch C: lossC + epilogue

// -------- device scratch (allocation-free, self-cleaning) --------
// Statically zero-init at load; invariant: every kernel_launch call both
// begins and ends with d_cnt/d_p2/d_loss/d_done_all zeroed.
//   d_cnt  : zeroed by launch-C epilogue (consumed by sort + obsA)
//   d_p2   : zeroed by lossC blocks (after consumption)
//   d_loss, d_done_all : zeroed by launch-C epilogue
//   d_p1, d_lst, d_order : fully overwritten each call
__device__ float  d_p2[T0_C];
__device__ float  d_p1[T1_R];
__device__ int    d_cnt[NG];
__device__ int    d_lst[NG * CAP];
__device__ int    d_order[NG];   // groups sorted by descending cnt (LPT)
__device__ double d_loss[3];     // [0]=sumsq loss_a, [1]=sumsq loss_b, [2]=sumsq loss_c
__device__ int    d_done_all;

// -------- block reduction (sum), result valid on thread 0 --------
__device__ __forceinline__ float block_reduce_sum(float v) {
    __shared__ float s[32];
    int lane = threadIdx.x & 31;
    int wid  = threadIdx.x >> 5;
    #pragma unroll
    for (int o = 16; o > 0; o >>= 1) v += __shfl_down_sync(0xffffffffu, v, o);
    if (lane == 0) s[wid] = v;
    __syncthreads();
    int nw = blockDim.x >> 5;
    v = (threadIdx.x < nw) ? s[threadIdx.x] : 0.0f;
    if (wid == 0) {
        #pragma unroll
        for (int o = 16; o > 0; o >>= 1) v += __shfl_down_sync(0xffffffffu, v, o);
    }
    return v;
}

// -------- Launch A: build (32 blks) + p1 (2048 blks, 2 rows each) ----------
__global__ void __launch_bounds__(256) k_buildp1(const int* __restrict__ idx0,
                                                 int n_idx,
                                                 const float* __restrict__ theta1) {
    int bid = blockIdx.x;
    int t = threadIdx.x;
    if (bid < BUILD_BLKS) {
        // ---- build per-group row lists (d_cnt arrives zeroed) ----
        int i = bid * 256 + t;
        if (i < T0_R && i < n_idx) {
            int g = idx0[i];
            if (g < 0) g = 0;
            if (g >= NG) g = NG - 1;      // defensive clamp: no OOB ever
            int slot = atomicAdd(&d_cnt[g], 1);
            if (slot < CAP) d_lst[g * CAP + slot] = i;
        }
    } else {
        // ---- p1: two rows per block; 128 threads/row x 16 loads (MLP=16) ----
        __shared__ float s[8];
        int b = bid - BUILD_BLKS;
        int half = t >> 7;                // 0 or 1
        int tt = t & 127;
        int r = 2 * b + half;
        const float* tr = theta1 + (size_t)r * T1_C + tt;
        float v[16];
        #pragma unroll
        for (int i = 0; i < 16; i++) v[i] = __ldcs(tr + i * 128);
        float local = 0.0f;
        #pragma unroll
        for (int i = 0; i < 16; i++) local += __expf(v[i]);
        #pragma unroll
        for (int o = 16; o > 0; o >>= 1) local += __shfl_down_sync(0xffffffffu, local, o);
        int wid = t >> 5;
        if ((t & 31) == 0) s[wid] = local;
        __syncthreads();
        if (t == 0)   d_p1[2 * b]     = s[0] + s[1] + s[2] + s[3];
        if (t == 128) d_p1[2 * b + 1] = s[4] + s[5] + s[6] + s[7];
    }
}

// -------- Launch A2: counting-sort groups by descending cnt (LPT order) ----
__global__ void __launch_bounds__(256) k_sort() {
    __shared__ int hist[CAP + 1];
    __shared__ int off[CAP + 1];
    int t = threadIdx.x;
    for (int i = t; i <= CAP; i += 256) hist[i] = 0;
    __syncthreads();
    for (int g = t; g < NG; g += 256) {
        int c = d_cnt[g];
        if (c > CAP) c = CAP;
        atomicAdd(&hist[c], 1);
    }
    __syncthreads();
    if (t == 0) {
        // descending: off[c] = number of groups with cnt > c
        int run = 0;
        for (int c = CAP; c >= 0; c--) { off[c] = run; run += hist[c]; }
    }
    __syncthreads();
    for (int g = t; g < NG; g += 256) {
        int c = d_cnt[g];
        if (c > CAP) c = CAP;
        int pos = atomicAdd(&off[c], 1);
        d_order[pos] = g;
    }
}

// -------- Launch B: obsA (4096, LPT-ordered) + obsB (512, needs only p1) ---
__global__ void __launch_bounds__(256) k_main(const float* __restrict__ theta0,
                                              const float* __restrict__ obs0,
                                              const float* __restrict__ mapping1,
                                              const float* __restrict__ obs1) {
    int bid = blockIdx.x;
    int t = threadIdx.x;

    if (bid < OBSA_BLKS) {
        // ---- obsA: (group, col-tile); heaviest groups first (LPT) ----
        __shared__ int s_rows[CAP];
        __shared__ int s_cnt;

        int g = d_order[bid >> 2];        // 4 tiles of each group adjacent
        int tile = bid & 3;
        int c0 = tile * 1024;

        if (t == 0) {
            int c = d_cnt[g];
            s_cnt = (c > CAP) ? CAP : c;
        }
        if (t < CAP) s_rows[t] = d_lst[g * CAP + t];

        // prefetch obs0 segment while the row list lands
        const float* orow = obs0 + (size_t)g * T0_C + c0;
        float o[4];
        #pragma unroll
        for (int i = 0; i < 4; i++) o[i] = orow[t + i * 256];

        __syncthreads();
        int cnt = s_cnt;

        float acc[4];
        #pragma unroll
        for (int i = 0; i < 4; i++) acc[i] = 0.0f;

        int j = 0;
        for (; j + 4 <= cnt; j += 4) {
            const float* p0 = theta0 + (size_t)s_rows[j]     * T0_C + c0 + t;
            const float* p1 = theta0 + (size_t)s_rows[j + 1] * T0_C + c0 + t;
            const float* p2 = theta0 + (size_t)s_rows[j + 2] * T0_C + c0 + t;
            const float* p3 = theta0 + (size_t)s_rows[j + 3] * T0_C + c0 + t;
            float v[16];
            #pragma unroll
            for (int i = 0; i < 4; i++) v[i]      = __ldcs(p0 + i * 256);
            #pragma unroll
            for (int i = 0; i < 4; i++) v[4 + i]  = __ldcs(p1 + i * 256);
            #pragma unroll
            for (int i = 0; i < 4; i++) v[8 + i]  = __ldcs(p2 + i * 256);
            #pragma unroll
            for (int i = 0; i < 4; i++) v[12 + i] = __ldcs(p3 + i * 256);
            #pragma unroll
            for (int i = 0; i < 4; i++)
                acc[i] += __expf(v[i]) + __expf(v[4 + i]) + __expf(v[8 + i]) + __expf(v[12 + i]);
        }
        for (; j + 2 <= cnt; j += 2) {
            const float* p0 = theta0 + (size_t)s_rows[j]     * T0_C + c0 + t;
            const float* p1 = theta0 + (size_t)s_rows[j + 1] * T0_C + c0 + t;
            float v[8];
            #pragma unroll
            for (int i = 0; i < 4; i++) v[i]     = __ldcs(p0 + i * 256);
            #pragma unroll
            for (int i = 0; i < 4; i++) v[4 + i] = __ldcs(p1 + i * 256);
            #pragma unroll
            for (int i = 0; i < 4; i++) acc[i] += __expf(v[i]) + __expf(v[4 + i]);
        }
        if (j < cnt) {
            const float* p0 = theta0 + (size_t)s_rows[j] * T0_C + c0 + t;
            float v[4];
            #pragma unroll
            for (int i = 0; i < 4; i++) v[i] = __ldcs(p0 + i * 256);
            #pragma unroll
            for (int i = 0; i < 4; i++) acc[i] += __expf(v[i]);
        }

        float local = 0.0f;
        #pragma unroll
        for (int i = 0; i < 4; i++) {
            int c = t + i * 256;
            atomicAdd(&d_p2[c0 + c], acc[i]);
            float diff = o[i] - acc[i];
            local += diff * diff;
        }
        float tot = block_reduce_sum(local);
        if (t == 0) atomicAdd(&d_loss[0], (double)tot);
    } else {
        // ---- obsB: mapping1 @ p1 + loss_b (p1 complete: prior launch) ----
        int b = bid - OBSA_BLKS;
        const float* mrow = mapping1 + (size_t)b * T1_R + t;
        float m[16], p[16];
        #pragma unroll
        for (int i = 0; i < 16; i++) m[i] = __ldcs(mrow + i * 256);
        #pragma unroll
        for (int i = 0; i < 16; i++) p[i] = d_p1[t + i * 256];
        float local = 0.0f;
        #pragma unroll
        for (int i = 0; i < 16; i++) local += m[i] * p[i];
        float tot = block_reduce_sum(local);
        if (t == 0) {
            float diff = obs1[b] - tot;
            atomicAdd(&d_loss[1], (double)(diff * diff));
        }
    }
}

// -------- Launch C: lossC (16 blks) + last-ticket final combine ------------
__global__ void __launch_bounds__(256) k_tail(const float* __restrict__ obs2,
                                              float* __restrict__ out) {
    int t = threadIdx.x;
    int c = blockIdx.x * 256 + t;
    float diff = obs2[c] - d_p2[c];
    d_p2[c] = 0.0f;                       // self-clean for next call
    float tot = block_reduce_sum(diff * diff);
    if (t == 0) atomicAdd(&d_loss[2], (double)tot);

    // ---- epilogue: last-ticket block combines + resets scratch ----
    __shared__ int is_last;
    if (t == 0) {
        __threadfence();
        int ticket = atomicAdd(&d_done_all, 1);
        is_last = (ticket == C_BLKS - 1);
    }
    __syncthreads();
    if (is_last) {
        __threadfence();
        #pragma unroll
        for (int i = 0; i < NG / 256; i++) d_cnt[t + i * 256] = 0;  // self-clean
        if (t == 0) {
            double la = *((volatile double*)&d_loss[0]);
            double lb = *((volatile double*)&d_loss[1]);
            double lc = *((volatile double*)&d_loss[2]);
            double loss_a = la / ((double)NG * (double)T0_C);
            double loss_b = lb / (double)NMAP;
            double loss_c = 0.5 * (lc / (double)T0_C);
            out[0] = (float)((loss_a + loss_b + loss_c) / 3.0);
            d_loss[0] = 0.0;              // self-clean for next call
            d_loss[1] = 0.0;
            d_loss[2] = 0.0;
            d_done_all = 0;
        }
    }
}

extern "C" void kernel_launch(void* const* d_in, const int* in_sizes, int n_in,
                              void* d_out, int out_size) {
    const float* theta0   = (const float*)d_in[0];
    const float* theta1   = (const float*)d_in[1];
    const float* obs0     = (const float*)d_in[2];
    const float* obs1     = (const float*)d_in[3];
    const float* obs2     = (const float*)d_in[4];
    const int*   idx0     = (const int*)d_in[5];   // int32: JAX x64 disabled
    const float* mapping1 = (const float*)d_in[6];
    float* out = (float*)d_out;

    k_buildp1<<<A_BLKS, 256>>>(idx0, in_sizes[5], theta1);
    k_sort<<<1, 256>>>();
    k_main<<<B_BLKS, 256>>>(theta0, obs0, mapping1, obs1);
    k_tail<<<C_BLKS, 256>>>(obs2, out);
}